// round 2
// baseline (speedup 1.0000x reference)
#include <cuda_runtime.h>
#include <cstdint>
#include <cstddef>

// Problem constants (reference: N=50000, D=128, E=800000, A=5)
#define NMAX 50000
#define DD 128
#define AA 5
#define HH 64

// ---------------- scratch (static device globals; no runtime allocation) ----
__device__ float g_B [NMAX*AA];   // sum of edge softmax vectors per src node
__device__ float g_xs[NMAX*AA];   // x @ w_weight[:, :128]^T
__device__ float g_xd[NMAX*AA];   // x @ w_weight[:, 128:]^T
__device__ float g_aw[NMAX*AA];   // node attention softmax weights
__device__ float g_h [NMAX*HH];   // relu(topo @ t1_w^T + t1_b)
__device__ int   g_deg[NMAX];
__device__ int   g_degmax;
__device__ int   g_is64;

// ---------------- Threefry-2x32 (exact JAX semantics) -----------------------
__host__ __device__ constexpr unsigned rotl32(unsigned v, int s) {
    return (v << s) | (v >> (32 - s));
}
struct TFout { unsigned a, b; };
__host__ __device__ constexpr TFout tf2x32(unsigned k0, unsigned k1,
                                           unsigned x0, unsigned x1) {
    unsigned ks[3] = {k0, k1, k0 ^ k1 ^ 0x1BD11BDAu};
    const int R0[4] = {13, 15, 26, 6};
    const int R1[4] = {17, 29, 16, 24};
    x0 += ks[0]; x1 += ks[1];
    for (int i = 0; i < 5; i++) {
        for (int j = 0; j < 4; j++) {
            int r = (i % 2 == 0) ? R0[j] : R1[j];
            x0 += x1; x1 = rotl32(x1, r); x1 ^= x0;
        }
        x0 += ks[(i + 1) % 3];
        x1 += ks[(i + 2) % 3] + (unsigned)(i + 1);
    }
    return {x0, x1};
}
// JAX >= 0.5 defaults jax_threefry_partitionable=True:
//   split(key(42), 2) is "foldlike": key_i = threefry2x32(key, hi=0, lo=i),
//   taking BOTH output words as the new key.
constexpr TFout KEY1 = tf2x32(0u, 42u, 0u, 0u);
constexpr TFout KEY2 = tf2x32(0u, 42u, 0u, 1u);

// partitionable random_bits(key, 32, (n,)): counter mode over 64-bit iota;
// for index n < 2^32: bits = out0 ^ out1 of threefry2x32(key, 0, n)
__device__ __forceinline__ float jax_uniform01(unsigned key0, unsigned key1,
                                               unsigned n) {
    TFout r = tf2x32(key0, key1, 0u, n);
    unsigned bits = r.a ^ r.b;
    return __uint_as_float(0x3F800000u | (bits >> 9)) - 1.0f;
}

// ---------------- edge index loader (int32/int64 runtime-detected) ----------
__device__ __forceinline__ int ld_edge(const void* ei, long long pos, int is64) {
    return is64 ? (int)__ldg(((const long long*)ei) + pos)
                : __ldg(((const int*)ei) + pos);
}

// ---------------- K0: zero scratch + detect index dtype ---------------------
__global__ void k_init(const int* ei32, long long n_elems, int N) {
    long long i = (long long)blockIdx.x * blockDim.x + threadIdx.x;
    if (i < (long long)N * AA) g_B[i] = 0.0f;
    if (i < N)                 g_deg[i] = 0;
    if (i == 0) {
        g_degmax = 0;
        // int64 little-endian => high 32-bit word of each entry is 0
        long long cnt = n_elems / 2; if (cnt > 64) cnt = 64;
        int orv = 0;
        for (long long t = 0; t < cnt; t++) orv |= ei32[2 * t + 1];
        g_is64 = (orv == 0) ? 1 : 0;
    }
}

// ---------------- K1: degree histogram over src ------------------------------
__global__ void k_degree(const void* ei, long long E) {
    long long e = (long long)blockIdx.x * blockDim.x + threadIdx.x;
    if (e >= E) return;
    int is64 = g_is64;
    int s = ld_edge(ei, e, is64);
    atomicAdd(&g_deg[s], 1);
}

// ---------------- K2: max(degree) --------------------------------------------
__global__ void k_degmax(int N) {
    int v = 0;
    for (int i = blockIdx.x * blockDim.x + threadIdx.x; i < N;
         i += gridDim.x * blockDim.x)
        v = max(v, g_deg[i]);
    for (int o = 16; o; o >>= 1) v = max(v, __shfl_xor_sync(0xffffffffu, v, o));
    __shared__ int sm[8];
    if ((threadIdx.x & 31) == 0) sm[threadIdx.x >> 5] = v;
    __syncthreads();
    if (threadIdx.x < 8) {
        int t = sm[threadIdx.x];
        for (int o = 4; o; o >>= 1) t = max(t, __shfl_xor_sync(0xffu, t, o));
        if (threadIdx.x == 0) atomicMax(&g_degmax, t);
    }
}

// ---------------- K3: per-node precompute (warp per node) --------------------
// attn softmax weights, xs/xd projections, topo features -> hidden h[64]
__global__ void __launch_bounds__(256)
k_nodeA(const float* __restrict__ x,
        const float* __restrict__ attn_w, const float* __restrict__ attn_b,
        const float* __restrict__ w_w,
        const float* __restrict__ t1w, const float* __restrict__ t1b,
        int N, float Ef) {
    __shared__ float s_attn[AA * DD];      // 640
    __shared__ float s_w[AA * 2 * DD];     // 1280
    __shared__ float s_t1w[HH * AA];       // 320
    __shared__ float s_t1b[HH];
    __shared__ float s_ab[AA];
    int tid = threadIdx.x;
    for (int i = tid; i < AA * DD;     i += blockDim.x) s_attn[i] = attn_w[i];
    for (int i = tid; i < AA * 2 * DD; i += blockDim.x) s_w[i]    = w_w[i];
    for (int i = tid; i < HH * AA;     i += blockDim.x) s_t1w[i]  = t1w[i];
    for (int i = tid; i < HH;          i += blockDim.x) s_t1b[i]  = t1b[i];
    if (tid < AA) s_ab[tid] = attn_b[tid];
    __syncthreads();

    int warp = tid >> 5, lane = tid & 31;
    int n = blockIdx.x * 8 + warp;
    if (n >= N) return;

    float4 xv = ((const float4*)x)[(size_t)n * 32 + lane];

    float pa[AA], ps[AA], pd[AA];
    const float4* a4 = (const float4*)s_attn;
    const float4* w4 = (const float4*)s_w;
#pragma unroll
    for (int k = 0; k < AA; k++) {
        float4 av = a4[k * 32 + lane];
        pa[k] = xv.x * av.x + xv.y * av.y + xv.z * av.z + xv.w * av.w;
        float4 sv = w4[k * 64 + lane];
        ps[k] = xv.x * sv.x + xv.y * sv.y + xv.z * sv.z + xv.w * sv.w;
        float4 dv = w4[k * 64 + 32 + lane];
        pd[k] = xv.x * dv.x + xv.y * dv.y + xv.z * dv.z + xv.w * dv.w;
    }
#pragma unroll
    for (int k = 0; k < AA; k++) {
#pragma unroll
        for (int o = 16; o; o >>= 1) {
            pa[k] += __shfl_xor_sync(0xffffffffu, pa[k], o);
            ps[k] += __shfl_xor_sync(0xffffffffu, ps[k], o);
            pd[k] += __shfl_xor_sync(0xffffffffu, pd[k], o);
        }
    }
    // attention softmax (all lanes redundantly; tiny)
    float la[AA];
#pragma unroll
    for (int k = 0; k < AA; k++) la[k] = pa[k] + s_ab[k];
    float m = la[0];
#pragma unroll
    for (int k = 1; k < AA; k++) m = fmaxf(m, la[k]);
    float ev[AA]; float sum = 0.0f;
#pragma unroll
    for (int k = 0; k < AA; k++) { ev[k] = __expf(la[k] - m); sum += ev[k]; }
    float inv = 1.0f / sum;
    if (lane == 0) {
#pragma unroll
        for (int k = 0; k < AA; k++) {
            g_aw[n * AA + k] = ev[k] * inv;
            g_xs[n * AA + k] = ps[k];
            g_xd[n * AA + k] = pd[k];
        }
    }
    // topology features in lane 0, broadcast
    float t0 = 0, t1v = 0, t2v = 0, t3v = 0, t4v = 0;
    if (lane == 0) {
        float deg   = (float)g_deg[n];
        float dmaxf = (float)g_degmax;
        float meanf = Ef / (float)N;
        t0  = deg / (dmaxf + 1e-6f);
        t2v = deg / (Ef + 1e-6f);
        t3v = 1.0f / (1.0f + __expf(-(deg - meanf)));
        t1v = jax_uniform01(KEY1.a, KEY1.b, (unsigned)n) * 0.5f + 0.25f;
        t4v = jax_uniform01(KEY2.a, KEY2.b, (unsigned)n);
    }
    t0  = __shfl_sync(0xffffffffu, t0, 0);
    t1v = __shfl_sync(0xffffffffu, t1v, 0);
    t2v = __shfl_sync(0xffffffffu, t2v, 0);
    t3v = __shfl_sync(0xffffffffu, t3v, 0);
    t4v = __shfl_sync(0xffffffffu, t4v, 0);
    float tv[5] = {t0, t1v, t2v, t3v, t4v};
#pragma unroll
    for (int r = 0; r < 2; r++) {
        int j = lane + r * 32;
        float hh = s_t1b[j];
#pragma unroll
        for (int i = 0; i < 5; i++) hh += tv[i] * s_t1w[j * 5 + i];
        g_h[(size_t)n * HH + j] = fmaxf(hh, 0.0f);
    }
}

// ---------------- K4: edge kernel (warp per edge, grid-stride) ---------------
__global__ void __launch_bounds__(256)
k_edge(const void* __restrict__ ei, long long E,
       const float* __restrict__ anchor, const float* __restrict__ w_b,
       float* __restrict__ outE) {
    int is64 = g_is64;
    int lane = threadIdx.x & 31;
    long long warpId = ((long long)blockIdx.x * blockDim.x + threadIdx.x) >> 5;
    long long nWarps = ((long long)gridDim.x * blockDim.x) >> 5;

    float4 a4[AA];  // anchor_prompt columns 4*lane..4*lane+3, register-resident
#pragma unroll
    for (int k = 0; k < AA; k++) a4[k] = ((const float4*)anchor)[k * 32 + lane];
    float wb = (lane < AA) ? __ldg(&w_b[lane]) : 0.0f;

    for (long long e = warpId; e < E; e += nWarps) {
        int src = ld_edge(ei, e, is64);
        int dst = ld_edge(ei, E + e, is64);
        float l = -1e30f;
        if (lane < AA) {
            l = __ldg(&g_xs[(size_t)src * AA + lane]) +
                __ldg(&g_xd[(size_t)dst * AA + lane]) + wb;
            l = (l > 0.0f) ? l : 0.01f * l;   // leaky_relu
        }
        float mx = l;
        mx = fmaxf(mx, __shfl_xor_sync(0xffffffffu, mx, 1));
        mx = fmaxf(mx, __shfl_xor_sync(0xffffffffu, mx, 2));
        mx = fmaxf(mx, __shfl_xor_sync(0xffffffffu, mx, 4));
        float ex = (lane < AA) ? __expf(l - mx) : 0.0f;
        float s = ex;
        s += __shfl_xor_sync(0xffffffffu, s, 1);
        s += __shfl_xor_sync(0xffffffffu, s, 2);
        s += __shfl_xor_sync(0xffffffffu, s, 4);
        float b = ex / s;
        if (lane < AA) atomicAdd(&g_B[(size_t)src * AA + lane], b);
        float b0 = __shfl_sync(0xffffffffu, b, 0);
        float b1 = __shfl_sync(0xffffffffu, b, 1);
        float b2 = __shfl_sync(0xffffffffu, b, 2);
        float b3 = __shfl_sync(0xffffffffu, b, 3);
        float b4 = __shfl_sync(0xffffffffu, b, 4);
        float4 o;
        o.x = b0*a4[0].x + b1*a4[1].x + b2*a4[2].x + b3*a4[3].x + b4*a4[4].x;
        o.y = b0*a4[0].y + b1*a4[1].y + b2*a4[2].y + b3*a4[3].y + b4*a4[4].y;
        o.z = b0*a4[0].z + b1*a4[1].z + b2*a4[2].z + b3*a4[3].z + b4*a4[4].z;
        o.w = b0*a4[0].w + b1*a4[1].w + b2*a4[2].w + b3*a4[3].w + b4*a4[4].w;
        ((float4*)outE)[(size_t)e * 32 + lane] = o;
    }
}

// ---------------- K5: final per-node (thread owns one output column) ---------
__global__ void __launch_bounds__(256, 2)
k_final(const float* __restrict__ x,
        const float* __restrict__ node_anchor, const float* __restrict__ anchor,
        const float* __restrict__ t2w, const float* __restrict__ t2b,
        float* __restrict__ outF, int N) {
    int lane = threadIdx.x & 31;
    int gw = (int)((blockIdx.x * blockDim.x + threadIdx.x) >> 5);
    int stream = gw >> 2;           // node stream id
    int cg = gw & 3;                // column group (0..3)
    int nStreams = (int)((gridDim.x * blockDim.x) >> 7);
    int col = cg * 32 + lane;

    float wreg[HH];                 // t2_w row for this output column
#pragma unroll
    for (int j4 = 0; j4 < 16; j4++) {
        float4 wv = ((const float4*)t2w)[(size_t)col * 16 + j4];
        wreg[4*j4+0] = wv.x; wreg[4*j4+1] = wv.y;
        wreg[4*j4+2] = wv.z; wreg[4*j4+3] = wv.w;
    }
    float areg[AA], nareg[AA];
#pragma unroll
    for (int k = 0; k < AA; k++) {
        areg[k]  = __ldg(&anchor[k * DD + col]);
        nareg[k] = __ldg(&node_anchor[k * DD + col]);
    }
    float bias = __ldg(&t2b[col]);

    for (int n = stream; n < N; n += nStreams) {
        float acc = bias;
        const float4* h4 = (const float4*)(g_h + (size_t)n * HH);
#pragma unroll
        for (int j4 = 0; j4 < 16; j4++) {
            float4 hv = h4[j4];     // uniform address across warp -> broadcast
            acc += hv.x * wreg[4*j4+0] + hv.y * wreg[4*j4+1]
                 + hv.z * wreg[4*j4+2] + hv.w * wreg[4*j4+3];
        }
        float agg = 0.0f, np = 0.0f;
#pragma unroll
        for (int k = 0; k < AA; k++) {
            agg += g_B [(size_t)n * AA + k] * areg[k];
            np  += g_aw[(size_t)n * AA + k] * nareg[k];
        }
        float xv = x[(size_t)n * DD + col];
        outF[(size_t)n * DD + col] = xv + np + acc * agg;
    }
}

// ---------------- launch ------------------------------------------------------
extern "C" void kernel_launch(void* const* d_in, const int* in_sizes, int n_in,
                              void* d_out, int out_size) {
    const float* x           = (const float*)d_in[0];
    const void*  ei          = d_in[1];
    // d_in[2] = layer (always 0; params provided are layer-0) — unused
    const float* anchor      = (const float*)d_in[3];
    const float* w_w         = (const float*)d_in[4];
    const float* w_b         = (const float*)d_in[5];
    const float* node_anchor = (const float*)d_in[6];
    const float* attn_w      = (const float*)d_in[7];
    const float* attn_b      = (const float*)d_in[8];
    const float* t1w         = (const float*)d_in[9];
    const float* t1b         = (const float*)d_in[10];
    const float* t2w         = (const float*)d_in[11];
    const float* t2b         = (const float*)d_in[12];

    int       N  = in_sizes[0] / DD;
    long long E  = (long long)in_sizes[1] / 2;
    float     Ef = (float)E;

    float* outF = (float*)d_out;                  // final_x [N, D]
    float* outE = outF + (size_t)N * DD;          // edge_prompt [E, D]

    int initElems = N * AA;
    k_init  <<<(initElems + 255) / 256, 256>>>((const int*)ei,
                                               (long long)in_sizes[1], N);
    k_degree<<<(unsigned)((E + 255) / 256), 256>>>(ei, E);
    k_degmax<<<128, 256>>>(N);
    k_nodeA <<<(N + 7) / 8, 256>>>(x, attn_w, attn_b, w_w, t1w, t1b, N, Ef);
    k_edge  <<<1184, 256>>>(ei, E, anchor, w_b, outE);
    k_final <<<296, 256>>>(x, node_anchor, anchor, t2w, t2b, outF, N);
}

// round 3
// speedup vs baseline: 1.7800x; 1.7800x over previous
#include <cuda_runtime.h>
#include <cstdint>
#include <cstddef>

// Problem constants (reference: N=50000, D=128, E=800000, A=5)
#define NMAX 50000
#define DD 128
#define AA 5
#define HH 64

// ---------------- scratch (static device globals) ----------------------------
__device__ float g_B4 [NMAX*4];   // sum of edge softmax (first 4 comps) per src
__device__ float g_xs8[NMAX*8];   // x @ w_weight[:, :128]^T + w_bias (padded)
__device__ float g_xd8[NMAX*8];   // x @ w_weight[:, 128:]^T (padded)
__device__ float g_aw8[NMAX*8];   // node attention softmax weights (padded)
__device__ float g_h  [NMAX*HH];  // relu(topo @ t1_w^T + t1_b)
__device__ int   g_deg[NMAX];
__device__ int   g_degmax;
__device__ int   g_is64;

// ---------------- Threefry-2x32 (JAX partitionable semantics) ----------------
__host__ __device__ constexpr unsigned rotl32(unsigned v, int s) {
    return (v << s) | (v >> (32 - s));
}
struct TFout { unsigned a, b; };
__host__ __device__ constexpr TFout tf2x32(unsigned k0, unsigned k1,
                                           unsigned x0, unsigned x1) {
    unsigned ks[3] = {k0, k1, k0 ^ k1 ^ 0x1BD11BDAu};
    const int R0[4] = {13, 15, 26, 6};
    const int R1[4] = {17, 29, 16, 24};
    x0 += ks[0]; x1 += ks[1];
    for (int i = 0; i < 5; i++) {
        for (int j = 0; j < 4; j++) {
            int r = (i % 2 == 0) ? R0[j] : R1[j];
            x0 += x1; x1 = rotl32(x1, r); x1 ^= x0;
        }
        x0 += ks[(i + 1) % 3];
        x1 += ks[(i + 2) % 3] + (unsigned)(i + 1);
    }
    return {x0, x1};
}
// split(key(42)) foldlike: key_i = threefry(key, hi=0, lo=i), both words
constexpr TFout KEY1 = tf2x32(0u, 42u, 0u, 0u);
constexpr TFout KEY2 = tf2x32(0u, 42u, 0u, 1u);

__device__ __forceinline__ float jax_uniform01(unsigned key0, unsigned key1,
                                               unsigned n) {
    TFout r = tf2x32(key0, key1, 0u, n);
    unsigned bits = r.a ^ r.b;
    return __uint_as_float(0x3F800000u | (bits >> 9)) - 1.0f;
}

// ---------------- edge index loader (int32/int64 runtime-detected) ----------
__device__ __forceinline__ int ld_edge(const void* ei, long long pos, int is64) {
    return is64 ? (int)__ldg(((const long long*)ei) + pos)
                : __ldg(((const int*)ei) + pos);
}

// ---------------- K0: zero scratch + detect index dtype ---------------------
__global__ void k_init(const int* ei32, long long n_elems, int N) {
    long long i = (long long)blockIdx.x * blockDim.x + threadIdx.x;
    if (i < (long long)N * 4) g_B4[i] = 0.0f;
    if (i < N)                g_deg[i] = 0;
    if (i == 0) {
        g_degmax = 0;
        long long cnt = n_elems / 2; if (cnt > 64) cnt = 64;
        int orv = 0;
        for (long long t = 0; t < cnt; t++) orv |= ei32[2 * t + 1];
        g_is64 = (orv == 0) ? 1 : 0;
    }
}

// ---------------- K1: degree histogram over src -------------------------------
__global__ void k_degree(const void* ei, long long E) {
    long long e = (long long)blockIdx.x * blockDim.x + threadIdx.x;
    if (e >= E) return;
    int s = ld_edge(ei, e, g_is64);
    atomicAdd(&g_deg[s], 1);
}

// ---------------- K2: max(degree) ---------------------------------------------
__global__ void k_degmax(int N) {
    int v = 0;
    for (int i = blockIdx.x * blockDim.x + threadIdx.x; i < N;
         i += gridDim.x * blockDim.x)
        v = max(v, g_deg[i]);
    for (int o = 16; o; o >>= 1) v = max(v, __shfl_xor_sync(0xffffffffu, v, o));
    __shared__ int sm[8];
    if ((threadIdx.x & 31) == 0) sm[threadIdx.x >> 5] = v;
    __syncthreads();
    if (threadIdx.x < 8) {
        int t = sm[threadIdx.x];
        for (int o = 4; o; o >>= 1) t = max(t, __shfl_xor_sync(0xffu, t, o));
        if (threadIdx.x == 0) atomicMax(&g_degmax, t);
    }
}

// ---------------- K3: per-node precompute (THREAD per node) -------------------
// No cross-lane ops: all weights are uniform smem broadcasts; all accumulators
// register-resident per thread.
__global__ void __launch_bounds__(256)
k_nodeA(const float* __restrict__ x,
        const float* __restrict__ attn_w, const float* __restrict__ attn_b,
        const float* __restrict__ w_w,  const float* __restrict__ w_b,
        const float* __restrict__ t1w,  const float* __restrict__ t1b,
        int N, float Ef) {
    __shared__ float4 s_attn[AA * 32];   // [5][128] as float4
    __shared__ float4 s_w[AA * 64];      // [5][256] as float4
    __shared__ float4 s_t1wT[AA * 16];   // transposed: [5][64] as float4
    __shared__ float4 s_t1b4[16];
    __shared__ float  s_ab[AA], s_wb[AA];
    int tid = threadIdx.x;
    for (int i = tid; i < AA * 32; i += 256) s_attn[i] = ((const float4*)attn_w)[i];
    for (int i = tid; i < AA * 64; i += 256) s_w[i]    = ((const float4*)w_w)[i];
    for (int idx = tid; idx < AA * HH; idx += 256) {
        int i = idx / HH, j = idx % HH;                // t1w is [64][5]
        ((float*)s_t1wT)[i * HH + j] = t1w[j * AA + i];
    }
    for (int i = tid; i < 16; i += 256) s_t1b4[i] = ((const float4*)t1b)[i];
    if (tid < AA) { s_ab[tid] = attn_b[tid]; s_wb[tid] = w_b[tid]; }
    __syncthreads();

    int n = blockIdx.x * 256 + tid;
    if (n >= N) return;

    float pa[AA], ps[AA], pd[AA];
#pragma unroll
    for (int k = 0; k < AA; k++) { pa[k] = s_ab[k]; ps[k] = s_wb[k]; pd[k] = 0.f; }

    const float4* xr = ((const float4*)x) + (size_t)n * 32;
#pragma unroll 4
    for (int c = 0; c < 32; c++) {
        float4 xv = __ldg(xr + c);
#pragma unroll
        for (int k = 0; k < AA; k++) {
            float4 av = s_attn[k * 32 + c];
            pa[k] += xv.x * av.x + xv.y * av.y + xv.z * av.z + xv.w * av.w;
            float4 sv = s_w[k * 64 + c];
            ps[k] += xv.x * sv.x + xv.y * sv.y + xv.z * sv.z + xv.w * sv.w;
            float4 dv = s_w[k * 64 + 32 + c];
            pd[k] += xv.x * dv.x + xv.y * dv.y + xv.z * dv.z + xv.w * dv.w;
        }
    }
    // attention softmax (per-thread, registers)
    float m = pa[0];
#pragma unroll
    for (int k = 1; k < AA; k++) m = fmaxf(m, pa[k]);
    float ev[AA], sum = 0.f;
#pragma unroll
    for (int k = 0; k < AA; k++) { ev[k] = __expf(pa[k] - m); sum += ev[k]; }
    float inv = __fdividef(1.0f, sum);

    float4* awp = (float4*)(g_aw8 + (size_t)n * 8);
    awp[0] = make_float4(ev[0]*inv, ev[1]*inv, ev[2]*inv, ev[3]*inv);
    g_aw8[(size_t)n * 8 + 4] = ev[4] * inv;
    float4* xsp = (float4*)(g_xs8 + (size_t)n * 8);
    xsp[0] = make_float4(ps[0], ps[1], ps[2], ps[3]);
    g_xs8[(size_t)n * 8 + 4] = ps[4];
    float4* xdp = (float4*)(g_xd8 + (size_t)n * 8);
    xdp[0] = make_float4(pd[0], pd[1], pd[2], pd[3]);
    g_xd8[(size_t)n * 8 + 4] = pd[4];

    // topology features (per-thread)
    float deg   = (float)__ldg(&g_deg[n]);
    float dmaxf = (float)g_degmax;
    float meanf = Ef / (float)N;
    float tv[5];
    tv[0] = deg / (dmaxf + 1e-6f);
    tv[1] = jax_uniform01(KEY1.a, KEY1.b, (unsigned)n) * 0.5f + 0.25f;
    tv[2] = deg / (Ef + 1e-6f);
    tv[3] = 1.0f / (1.0f + __expf(-(deg - meanf)));
    tv[4] = jax_uniform01(KEY2.a, KEY2.b, (unsigned)n);

    float4* hout = (float4*)(g_h + (size_t)n * HH);
#pragma unroll
    for (int jc = 0; jc < 16; jc++) {
        float4 hv = s_t1b4[jc];
#pragma unroll
        for (int i = 0; i < AA; i++) {
            float4 wv = s_t1wT[i * 16 + jc];
            hv.x += tv[i] * wv.x; hv.y += tv[i] * wv.y;
            hv.z += tv[i] * wv.z; hv.w += tv[i] * wv.w;
        }
        hv.x = fmaxf(hv.x, 0.f); hv.y = fmaxf(hv.y, 0.f);
        hv.z = fmaxf(hv.z, 0.f); hv.w = fmaxf(hv.w, 0.f);
        hout[jc] = hv;
    }
}

// ---------------- K4: edge kernel — thread-per-edge softmax, warp store ------
__global__ void __launch_bounds__(256)
k_edge(const void* __restrict__ ei, long long E,
       const float* __restrict__ anchor, float* __restrict__ outE) {
    __shared__ float s_b[256 * 5];
    int tid  = threadIdx.x;
    int lane = tid & 31;
    int warp = tid >> 5;
    int is64 = g_is64;

    // anchor columns 4*lane..4*lane+3 register-resident (L1-hot across blocks)
    float4 a0 = __ldg(((const float4*)anchor) + 0 * 32 + lane);
    float4 a1 = __ldg(((const float4*)anchor) + 1 * 32 + lane);
    float4 a2 = __ldg(((const float4*)anchor) + 2 * 32 + lane);
    float4 a3 = __ldg(((const float4*)anchor) + 3 * 32 + lane);
    float4 a4 = __ldg(((const float4*)anchor) + 4 * 32 + lane);

    long long e = (long long)blockIdx.x * 256 + tid;
    if (e < E) {
        int src = ld_edge(ei, e, is64);
        int dst = ld_edge(ei, E + e, is64);
        float4 s4 = __ldg((const float4*)(g_xs8 + (size_t)src * 8));
        float  s5 = __ldg(g_xs8 + (size_t)src * 8 + 4);
        float4 d4 = __ldg((const float4*)(g_xd8 + (size_t)dst * 8));
        float  d5 = __ldg(g_xd8 + (size_t)dst * 8 + 4);
        float l[5];
        l[0] = s4.x + d4.x; l[1] = s4.y + d4.y; l[2] = s4.z + d4.z;
        l[3] = s4.w + d4.w; l[4] = s5 + d5;
#pragma unroll
        for (int k = 0; k < 5; k++) l[k] = fmaxf(l[k], 0.01f * l[k]); // leaky
        float m = l[0];
#pragma unroll
        for (int k = 1; k < 5; k++) m = fmaxf(m, l[k]);
        float ev[5], sum = 0.f;
#pragma unroll
        for (int k = 0; k < 5; k++) { ev[k] = __expf(l[k] - m); sum += ev[k]; }
        float inv = __fdividef(1.0f, sum);
        float b[5];
#pragma unroll
        for (int k = 0; k < 5; k++) b[k] = ev[k] * inv;
        // scatter only first 4 components; 5th derived in k_final from degree
#pragma unroll
        for (int k = 0; k < 4; k++) atomicAdd(&g_B4[(size_t)src * 4 + k], b[k]);
#pragma unroll
        for (int k = 0; k < 5; k++) s_b[tid * 5 + k] = b[k];   // stride 5: no conflicts
    }
    __syncwarp();

    long long base = (long long)blockIdx.x * 256 + warp * 32;
    float4* o4 = (float4*)outE;
#pragma unroll 4
    for (int j = 0; j < 32; j++) {
        long long eid = base + j;
        if (eid >= E) break;
        int sb = (warp * 32 + j) * 5;            // uniform -> broadcast LDS
        float b0 = s_b[sb + 0], b1 = s_b[sb + 1], b2 = s_b[sb + 2];
        float b3 = s_b[sb + 3], b4 = s_b[sb + 4];
        float4 o;
        o.x = b0*a0.x + b1*a1.x + b2*a2.x + b3*a3.x + b4*a4.x;
        o.y = b0*a0.y + b1*a1.y + b2*a2.y + b3*a3.y + b4*a4.y;
        o.z = b0*a0.z + b1*a1.z + b2*a2.z + b3*a3.z + b4*a4.z;
        o.w = b0*a0.w + b1*a1.w + b2*a2.w + b3*a3.w + b4*a4.w;
        __stcs(o4 + (size_t)eid * 32 + lane, o);  // streaming store
    }
}

// ---------------- K5: final per-node (thread owns one output column) ---------
__global__ void __launch_bounds__(256, 2)
k_final(const float* __restrict__ x,
        const float* __restrict__ node_anchor, const float* __restrict__ anchor,
        const float* __restrict__ t2w, const float* __restrict__ t2b,
        float* __restrict__ outF, int N) {
    int lane = threadIdx.x & 31;
    int gw = (int)((blockIdx.x * blockDim.x + threadIdx.x) >> 5);
    int stream = gw >> 2;
    int cg = gw & 3;
    int nStreams = (int)((gridDim.x * blockDim.x) >> 7);
    int col = cg * 32 + lane;

    float wreg[HH];
#pragma unroll
    for (int j4 = 0; j4 < 16; j4++) {
        float4 wv = ((const float4*)t2w)[(size_t)col * 16 + j4];
        wreg[4*j4+0] = wv.x; wreg[4*j4+1] = wv.y;
        wreg[4*j4+2] = wv.z; wreg[4*j4+3] = wv.w;
    }
    float areg[AA], nareg[AA];
#pragma unroll
    for (int k = 0; k < AA; k++) {
        areg[k]  = __ldg(&anchor[k * DD + col]);
        nareg[k] = __ldg(&node_anchor[k * DD + col]);
    }
    float bias = __ldg(&t2b[col]);

    for (int n = stream; n < N; n += nStreams) {
        float acc = bias;
        const float4* h4 = (const float4*)(g_h + (size_t)n * HH);
#pragma unroll
        for (int j4 = 0; j4 < 16; j4++) {
            float4 hv = h4[j4];      // uniform address -> broadcast
            acc += hv.x * wreg[4*j4+0] + hv.y * wreg[4*j4+1]
                 + hv.z * wreg[4*j4+2] + hv.w * wreg[4*j4+3];
        }
        float4 B   = *(const float4*)(g_B4 + (size_t)n * 4);
        float deg  = (float)g_deg[n];
        float B4v  = deg - B.x - B.y - B.z - B.w;
        float agg  = B.x*areg[0] + B.y*areg[1] + B.z*areg[2] + B.w*areg[3]
                   + B4v*areg[4];
        float4 aw4 = *(const float4*)(g_aw8 + (size_t)n * 8);
        float aw5  = g_aw8[(size_t)n * 8 + 4];
        float np   = aw4.x*nareg[0] + aw4.y*nareg[1] + aw4.z*nareg[2]
                   + aw4.w*nareg[3] + aw5*nareg[4];
        float xv = x[(size_t)n * DD + col];
        outF[(size_t)n * DD + col] = xv + np + acc * agg;
    }
}

// ---------------- launch ------------------------------------------------------
extern "C" void kernel_launch(void* const* d_in, const int* in_sizes, int n_in,
                              void* d_out, int out_size) {
    const float* x           = (const float*)d_in[0];
    const void*  ei          = d_in[1];
    const float* anchor      = (const float*)d_in[3];
    const float* w_w         = (const float*)d_in[4];
    const float* w_b         = (const float*)d_in[5];
    const float* node_anchor = (const float*)d_in[6];
    const float* attn_w      = (const float*)d_in[7];
    const float* attn_b      = (const float*)d_in[8];
    const float* t1w         = (const float*)d_in[9];
    const float* t1b         = (const float*)d_in[10];
    const float* t2w         = (const float*)d_in[11];
    const float* t2b         = (const float*)d_in[12];

    int       N  = in_sizes[0] / DD;
    long long E  = (long long)in_sizes[1] / 2;
    float     Ef = (float)E;

    float* outF = (float*)d_out;                  // final_x [N, D]
    float* outE = outF + (size_t)N * DD;          // edge_prompt [E, D]

    k_init  <<<(N * 4 + 255) / 256, 256>>>((const int*)ei,
                                           (long long)in_sizes[1], N);
    k_degree<<<(unsigned)((E + 255) / 256), 256>>>(ei, E);
    k_degmax<<<128, 256>>>(N);
    k_nodeA <<<(N + 255) / 256, 256>>>(x, attn_w, attn_b, w_w, w_b,
                                       t1w, t1b, N, Ef);
    k_edge  <<<(unsigned)((E + 255) / 256), 256>>>(ei, E, anchor, outE);
    k_final <<<296, 256>>>(x, node_anchor, anchor, t2w, t2b, outF, N);
}